// round 8
// baseline (speedup 1.0000x reference)
#include <cuda_runtime.h>
#include <cstdint>

// ---------------------------------------------------------------------------
// BiSpikeNet forward. T=8, B=16, F=262144.
//
// R2 skeleton (128 blocks x 1024 threads, membrane in 128 KiB SMEM, one-step
// L2 prefetch), but the per-batch 8-block software barrier is replaced by a
// HARDWARE CLUSTER: cluster_dims(8,1,1) == one batch. Per-step reduction:
// each block's lane0 stores its partial into all 8 blocks' SMEM via DSMEM
// (mapa + st.shared::cluster), barrier.cluster.arrive/wait, then every
// thread reads the 8 partials from LOCAL smem and computes 1/denom itself
// (same sequential order as R2 -> bitwise-identical denominator).
// No global state, single kernel launch, no software spin loops.
// ---------------------------------------------------------------------------

namespace {
constexpr int T_STEPS  = 8;
constexpr int BATCH    = 16;
constexpr int FDIM     = 1 << 18;              // 262144
constexpr int CSIZE    = 8;                    // blocks per batch = cluster
constexpr int NBLOCKS  = BATCH * CSIZE;        // 128
constexpr int NTHREADS = 1024;
constexpr int EPB      = FDIM / CSIZE;         // 32768 elems/block
constexpr int KG       = EPB / (NTHREADS * 4); // 8 float4 groups/thread
constexpr int NHEADS   = 4;
constexpr int HID      = 64;
constexpr int SMEM_DYN = EPB * 4;              // 128 KiB membrane
}

__device__ __forceinline__ void l2_prefetch(const void* p) {
    asm volatile("prefetch.global.L2 [%0];" :: "l"(p));
}
__device__ __forceinline__ uint32_t smem_u32(const void* p) {
    return (uint32_t)__cvta_generic_to_shared(p);
}
__device__ __forceinline__ void dsmem_st_f32(uint32_t laddr, uint32_t rank, float v) {
    uint32_t r;
    asm volatile("mapa.shared::cluster.u32 %0, %1, %2;" : "=r"(r) : "r"(laddr), "r"(rank));
    asm volatile("st.shared::cluster.f32 [%0], %1;" :: "r"(r), "f"(v) : "memory");
}
__device__ __forceinline__ void dsmem_st_u32(uint32_t laddr, uint32_t rank, uint32_t v) {
    uint32_t r;
    asm volatile("mapa.shared::cluster.u32 %0, %1, %2;" : "=r"(r) : "r"(laddr), "r"(rank));
    asm volatile("st.shared::cluster.u32 [%0], %1;" :: "r"(r), "r"(v) : "memory");
}
__device__ __forceinline__ void cluster_arrive() {
    asm volatile("barrier.cluster.arrive.aligned;" ::: "memory");
}
__device__ __forceinline__ void cluster_wait() {
    asm volatile("barrier.cluster.wait.aligned;" ::: "memory");
}

__global__ void __launch_bounds__(NTHREADS, 1) __cluster_dims__(CSIZE, 1, 1)
bispike_kernel(
    const float* __restrict__ x,
    const float* __restrict__ decay_p,
    const float* __restrict__ vth_p,
    const float* __restrict__ W1,
    const float* __restrict__ b1,
    const float* __restrict__ W2,
    const float* __restrict__ b2,
    const float* __restrict__ att_w,
    float* __restrict__ out)
{
    extern __shared__ float smem_dyn[];
    float4* s_m4 = reinterpret_cast<float4*>(smem_dyn);   // EPB floats

    __shared__ float        s_red[32];
    __shared__ unsigned int s_redc[32];
    __shared__ float        s_part[2][CSIZE];   // ping-pong partial |m| sums
    __shared__ unsigned int s_cnt[CSIZE][4];    // packed spike counts
    __shared__ float        s_h[NHEADS * HID];
    __shared__ float        s_maps[32];
    __shared__ float        s_aw[T_STEPS];

    const int tid  = threadIdx.x;
    const int lane = tid & 31;
    const int warp = tid >> 5;
    const int b    = blockIdx.x >> 3;            // batch == cluster id
    const int blk  = blockIdx.x & 7;             // rank within cluster
    const int f0   = blk * EPB;

    const float d    = 1.0f / (1.0f + expf(-decay_p[0]));
    const float vth  = vth_p[0];
    const float dvth = d * vth;

    unsigned int bits4[KG];                      // 4 elems x 8 step-bits/word
#pragma unroll
    for (int k = 0; k < KG; k++) bits4[k] = 0u;

    const float* xbase = x + (size_t)b * FDIM + f0;
    float inv_prev = 0.0f;

    // ---------------- temporal LIF loop ----------------
    for (int t = 0; t < T_STEPS; t++) {
        const float inv = inv_prev;
        const float4* xp = reinterpret_cast<const float4*>(
            xbase + (size_t)t * BATCH * FDIM);
        float sa0 = 0.f, sa1 = 0.f, sa2 = 0.f, sa3 = 0.f;
#pragma unroll
        for (int k = 0; k < KG; k++) {
            const int idx4 = k * NTHREADS + tid;
            float4 xv = xp[idx4];
            float xa[4] = {xv.x, xv.y, xv.z, xv.w};
            float ma[4];
            if (t == 0) {
#pragma unroll
                for (int j = 0; j < 4; j++) ma[j] = xa[j];
            } else {
                float4 mo = s_m4[idx4];
                float moa[4] = {mo.x, mo.y, mo.z, mo.w};
#pragma unroll
                for (int j = 0; j < 4; j++) {
                    float mn = moa[j] * inv;        // normalized m_{t-1}
                    bool  sp = (mn >= vth);
                    if (sp) bits4[k] |= (1u << (8 * j + (t - 1)));
                    ma[j] = fmaf(d, mn, xa[j]) - (sp ? dvth : 0.0f);
                }
            }
            s_m4[idx4] = make_float4(ma[0], ma[1], ma[2], ma[3]);
            sa0 += fabsf(ma[0]); sa1 += fabsf(ma[1]);
            sa2 += fabsf(ma[2]); sa3 += fabsf(ma[3]);
        }
        float sum_abs = (sa0 + sa1) + (sa2 + sa3);

        // L2 prefetch of x[t+1] (one per 128B line) while we reduce + sync
        if (t + 1 < T_STEPS && (lane & 7) == 0) {
            const float4* xn = reinterpret_cast<const float4*>(
                xbase + (size_t)(t + 1) * BATCH * FDIM);
#pragma unroll
            for (int k = 0; k < KG; k++)
                l2_prefetch(&xn[k * NTHREADS + tid]);
        }

        // block reduction of |m| sum (identical tree to R2)
#pragma unroll
        for (int off = 16; off > 0; off >>= 1)
            sum_abs += __shfl_xor_sync(0xffffffffu, sum_abs, off);
        if (lane == 0) s_red[warp] = sum_abs;
        __syncthreads();
        if (warp == 0) {
            float v = s_red[lane];
#pragma unroll
            for (int off = 16; off > 0; off >>= 1)
                v += __shfl_xor_sync(0xffffffffu, v, off);
            if (lane == 0) {
                // publish partial to slot[blk] of ALL cluster blocks (DSMEM)
                const uint32_t laddr = smem_u32(&s_part[t & 1][blk]);
#pragma unroll
                for (uint32_t r = 0; r < CSIZE; r++)
                    dsmem_st_f32(laddr, r, v);
            }
        }
        // cluster barrier: lane0's arrive releases its DSMEM stores;
        // wait acquires all blocks' stores.
        cluster_arrive();
        cluster_wait();

        // every thread computes the denominator itself (fixed order == R2)
        float tot = 0.0f;
#pragma unroll
        for (int i = 0; i < CSIZE; i++) tot += s_part[t & 1][i];
        float dnm = tot * (1.0f / (float)FDIM) + 1e-6f;
        inv_prev = 1.0f / dnm;
    }

    // ---------------- final step spikes (t = T-1) ----------------
    {
        const float inv = inv_prev;
#pragma unroll
        for (int k = 0; k < KG; k++) {
            float4 mo = s_m4[k * NTHREADS + tid];
            float moa[4] = {mo.x, mo.y, mo.z, mo.w};
#pragma unroll
            for (int j = 0; j < 4; j++)
                if (moa[j] * inv >= vth) bits4[k] |= (1u << (8 * j + 7));
        }
    }

    // ---------------- spike counts via popc (packed 2x16-bit) -------------
    {
        unsigned int cf[4];                      // final block counts (lane0)
#pragma unroll
        for (int q = 0; q < 4; q++) {
            unsigned int c_lo = 0, c_hi = 0;
            unsigned int m_lo = 0x01010101u << (2 * q);
            unsigned int m_hi = 0x01010101u << (2 * q + 1);
#pragma unroll
            for (int k = 0; k < KG; k++) {
                c_lo += __popc(bits4[k] & m_lo);
                c_hi += __popc(bits4[k] & m_hi);
            }
            unsigned int v = c_lo | (c_hi << 16);   // block count <= 32768: fits
#pragma unroll
            for (int off = 16; off > 0; off >>= 1)
                v += __shfl_xor_sync(0xffffffffu, v, off);
            if (lane == 0) s_redc[warp] = v;
            __syncthreads();
            unsigned int c = 0;
            if (warp == 0) {
                c = s_redc[lane];
#pragma unroll
                for (int off = 16; off > 0; off >>= 1)
                    c += __shfl_xor_sync(0xffffffffu, c, off);
            }
            cf[q] = c;                              // valid in warp0 lane0
            __syncthreads();
        }
        // warp0: broadcast cf, lanes 0-7 each write 4 words to rank==lane
        if (warp == 0) {
#pragma unroll
            for (int q = 0; q < 4; q++)
                cf[q] = __shfl_sync(0xffffffffu, cf[q], 0);
            if (lane < CSIZE) {
#pragma unroll
                for (int q = 0; q < 4; q++)
                    dsmem_st_u32(smem_u32(&s_cnt[blk][q]), (uint32_t)lane, cf[q]);
            }
        }
        cluster_arrive();
        cluster_wait();
    }

    // ---------------- tiny attention MLP (warp 0, per batch) --------------
    if (warp == 0) {
        float summ[T_STEPS];
#pragma unroll
        for (int q = 0; q < 4; q++) {
            unsigned int lo = 0, hi = 0;
#pragma unroll
            for (int i = 0; i < CSIZE; i++) {      // fixed order, local SMEM
                unsigned int v = s_cnt[i][q];
                lo += v & 0xffffu;
                hi += v >> 16;
            }
            summ[2 * q]     = (float)lo * (1.0f / (float)FDIM);
            summ[2 * q + 1] = (float)hi * (1.0f / (float)FDIM);
        }
#pragma unroll
        for (int r = 0; r < 8; r++) {
            int idx = r * 32 + lane;
            float acc = b1[idx];
#pragma unroll
            for (int t = 0; t < T_STEPS; t++)
                acc += summ[t] * W1[idx * T_STEPS + t];
            s_h[idx] = fmaxf(acc, 0.0f);
        }
        __syncwarp();
        {
            float acc = b2[lane];
            const int hb = (lane >> 3) * HID;
            const float* w2p = W2 + lane * HID;
#pragma unroll
            for (int hd = 0; hd < HID; hd++)
                acc += s_h[hb + hd] * w2p[hd];
            s_maps[lane] = acc * att_w[lane >> 3];
        }
        __syncwarp();
        if (lane == 0) {
            float w[T_STEPS];
            float mx = -1e30f;
#pragma unroll
            for (int t = 0; t < T_STEPS; t++) {
                w[t] = s_maps[t] + s_maps[8 + t] + s_maps[16 + t] + s_maps[24 + t];
                mx = fmaxf(mx, w[t]);
            }
            float ssum = 0.0f;
#pragma unroll
            for (int t = 0; t < T_STEPS; t++) { w[t] = expf(w[t] - mx); ssum += w[t]; }
            float invs = 1.0f / ssum;
#pragma unroll
            for (int t = 0; t < T_STEPS; t++) s_aw[t] = w[t] * invs;
        }
    }
    __syncthreads();

    float aw[T_STEPS];
#pragma unroll
    for (int t = 0; t < T_STEPS; t++) aw[t] = s_aw[t];

    // ---------------- output: out[b,f] = sum_t aw[t]*spike(t,f) -----------
    float4* op = reinterpret_cast<float4*>(out + (size_t)b * FDIM + f0);
#pragma unroll
    for (int k = 0; k < KG; k++) {
        unsigned int bt = bits4[k];
        float o[4];
#pragma unroll
        for (int j = 0; j < 4; j++) {
            float v = 0.0f;
#pragma unroll
            for (int t = 0; t < T_STEPS; t++)
                v += ((bt >> (8 * j + t)) & 1u) ? aw[t] : 0.0f;
            o[j] = v;
        }
        op[k * NTHREADS + tid] = make_float4(o[0], o[1], o[2], o[3]);
    }

    // no cross-cluster state; final cluster sync so no block exits while a
    // peer might still read its SMEM (s_cnt already consumed, but cheap+safe)
    cluster_arrive();
    cluster_wait();
}

extern "C" void kernel_launch(void* const* d_in, const int* in_sizes, int n_in,
                              void* d_out, int out_size) {
    (void)in_sizes; (void)n_in; (void)out_size;
    cudaFuncSetAttribute(bispike_kernel,
                         cudaFuncAttributeMaxDynamicSharedMemorySize, SMEM_DYN);
    bispike_kernel<<<NBLOCKS, NTHREADS, SMEM_DYN>>>(
        (const float*)d_in[0],   // x
        (const float*)d_in[1],   // decay_param
        (const float*)d_in[2],   // v_th
        (const float*)d_in[3],   // W1
        (const float*)d_in[4],   // b1
        (const float*)d_in[5],   // W2
        (const float*)d_in[6],   // b2
        (const float*)d_in[7],   // att_w
        (float*)d_out);
}

// round 9
// speedup vs baseline: 1.3644x; 1.3644x over previous
#include <cuda_runtime.h>

// ---------------------------------------------------------------------------
// BiSpikeNet forward. T=8, B=16, F=262144.  R2-winner skeleton, minus overhead:
//  - 128 blocks x 1024 threads, membrane in 128 KiB SMEM, one-step L2 prefetch
//  - per-batch 8-block spin barrier; every block re-reads the 8 partials and
//    sums them itself in fixed order (bitwise == R2 denominator)
//  - NEW: no reset kernel -- barrier counters are monotonic across launches
//    (each launch adds exactly 8; release when ctr >= (my_old|7)+1)
//  - NEW: spike counts popc'd from register bits at the end (not in the
//    per-step shuffle tree)
//  - NEW: the 8 partial reads at release are done by lanes 0-7 in parallel,
//    then summed sequentially via shuffles in the same order
// ---------------------------------------------------------------------------

namespace {
constexpr int T_STEPS        = 8;
constexpr int BATCH          = 16;
constexpr int FDIM           = 1 << 18;          // 262144
constexpr int BLKS_PER_BATCH = 8;
constexpr int NBLOCKS        = BATCH * BLKS_PER_BATCH;   // 128
constexpr int NTHREADS       = 1024;
constexpr int EPB            = FDIM / BLKS_PER_BATCH;    // 32768 elems/block
constexpr int KG             = EPB / (NTHREADS * 4);     // 8 float4 groups/thread
constexpr int NHEADS         = 4;
constexpr int HID            = 64;
constexpr int NBAR           = (T_STEPS + 1) * BATCH;    // 144 counters
constexpr int SMEM_DYN       = EPB * 4;                  // 128 KiB membrane
}

// Monotonic barrier counters: NEVER reset. Each launch adds exactly
// BLKS_PER_BATCH(=8) to each counter; a block that observed old=v on its own
// atomicAdd waits until ctr >= (v|7)+1. Launches on one stream are serialized,
// so partials are never overwritten while a previous launch still reads them.
__device__ unsigned int g_bar[NBAR];                      // zero-initialized once
__device__ float g_abs_part[T_STEPS][BATCH][BLKS_PER_BATCH];
__device__ unsigned int g_cnt_part[BATCH][BLKS_PER_BATCH][4];

__device__ __forceinline__ void l2_prefetch(const void* p) {
    asm volatile("prefetch.global.L2 [%0];" :: "l"(p));
}

__global__ void __launch_bounds__(NTHREADS, 1) bispike_kernel(
    const float* __restrict__ x,
    const float* __restrict__ decay_p,
    const float* __restrict__ vth_p,
    const float* __restrict__ W1,
    const float* __restrict__ b1,
    const float* __restrict__ W2,
    const float* __restrict__ b2,
    const float* __restrict__ att_w,
    float* __restrict__ out)
{
    extern __shared__ float smem_dyn[];
    float4* s_m4 = reinterpret_cast<float4*>(smem_dyn);     // EPB floats

    __shared__ float s_red[32];
    __shared__ unsigned int s_redc[32];
    __shared__ float s_h[NHEADS * HID];
    __shared__ float s_maps[32];
    __shared__ float s_aw[T_STEPS];
    __shared__ float s_invd;

    const int tid  = threadIdx.x;
    const int lane = tid & 31;
    const int warp = tid >> 5;
    const int b    = blockIdx.x >> 3;            // batch
    const int blk  = blockIdx.x & 7;             // slice within batch
    const int f0   = blk * EPB;

    const float d    = 1.0f / (1.0f + expf(-decay_p[0]));
    const float vth  = vth_p[0];
    const float dvth = d * vth;

    unsigned int bits4[KG];                      // 4 elems x 8 step-bits per word
#pragma unroll
    for (int k = 0; k < KG; k++) bits4[k] = 0u;

    const float* xbase = x + (size_t)b * FDIM + f0;
    float inv_prev = 0.0f;

    // ---------------- temporal LIF loop ----------------
    for (int t = 0; t < T_STEPS; t++) {
        const float inv = inv_prev;
        const float4* xp = reinterpret_cast<const float4*>(
            xbase + (size_t)t * BATCH * FDIM);
        float sa0 = 0.f, sa1 = 0.f, sa2 = 0.f, sa3 = 0.f;
#pragma unroll
        for (int k = 0; k < KG; k++) {
            const int idx4 = k * NTHREADS + tid;
            float4 xv = xp[idx4];
            float xa[4] = {xv.x, xv.y, xv.z, xv.w};
            float ma[4];
            if (t == 0) {
#pragma unroll
                for (int j = 0; j < 4; j++) ma[j] = xa[j];
            } else {
                float4 mo = s_m4[idx4];
                float moa[4] = {mo.x, mo.y, mo.z, mo.w};
#pragma unroll
                for (int j = 0; j < 4; j++) {
                    float mn = moa[j] * inv;        // normalized m_{t-1}
                    bool  sp = (mn >= vth);
                    if (sp) bits4[k] |= (1u << (8 * j + (t - 1)));
                    ma[j] = fmaf(d, mn, xa[j]) - (sp ? dvth : 0.0f);
                }
            }
            s_m4[idx4] = make_float4(ma[0], ma[1], ma[2], ma[3]);
            sa0 += fabsf(ma[0]); sa1 += fabsf(ma[1]);
            sa2 += fabsf(ma[2]); sa3 += fabsf(ma[3]);
        }
        float sum_abs = (sa0 + sa1) + (sa2 + sa3);

        // L2 prefetch of x[t+1] while we reduce + wait at the barrier
        // (one prefetch per 128B line: lanes 0,8,16,24 cover the warp span)
        if (t + 1 < T_STEPS && (lane & 7) == 0) {
            const float4* xn = reinterpret_cast<const float4*>(
                xbase + (size_t)(t + 1) * BATCH * FDIM);
#pragma unroll
            for (int k = 0; k < KG; k++)
                l2_prefetch(&xn[k * NTHREADS + tid]);
        }

        // deterministic block reduction of |m| sum (identical tree to R2)
#pragma unroll
        for (int off = 16; off > 0; off >>= 1)
            sum_abs += __shfl_xor_sync(0xffffffffu, sum_abs, off);
        if (lane == 0) s_red[warp] = sum_abs;
        __syncthreads();
        if (warp == 0) {
            float v = s_red[lane];
#pragma unroll
            for (int off = 16; off > 0; off >>= 1)
                v += __shfl_xor_sync(0xffffffffu, v, off);
            // ---- barrier: publish, arrive (monotonic), spin, gather ----
            unsigned int rel = 0;
            if (lane == 0) {
                *(volatile float*)&g_abs_part[t][b][blk] = v;
                __threadfence();
                unsigned int old = atomicAdd(&g_bar[t * BATCH + b], 1u);
                rel = (old | 7u) + 1u;                 // release threshold
                volatile unsigned int* ctr = &g_bar[t * BATCH + b];
                while (*ctr < rel) { }
            }
            __syncwarp();
            // lanes 0..7 load the 8 partials in parallel (one round trip)
            float part = 0.0f;
            if (lane < BLKS_PER_BATCH)
                part = *(volatile float*)&g_abs_part[t][b][lane];
            // sequential-order sum via shuffles (bitwise == R2)
            if (lane == 0) {
                float tot = 0.0f;
#pragma unroll
                for (int i = 0; i < BLKS_PER_BATCH; i++)
                    tot += __shfl_sync(0xffffffffu, part, i);
                float dnm = tot * (1.0f / (float)FDIM) + 1e-6f;
                s_invd = 1.0f / dnm;
            } else {
#pragma unroll
                for (int i = 0; i < BLKS_PER_BATCH; i++)
                    (void)__shfl_sync(0xffffffffu, part, i);
            }
        }
        __syncthreads();
        inv_prev = s_invd;
    }

    // ---------------- final step spikes (t = T-1) ----------------
    {
        const float inv = inv_prev;
#pragma unroll
        for (int k = 0; k < KG; k++) {
            float4 mo = s_m4[k * NTHREADS + tid];
            float moa[4] = {mo.x, mo.y, mo.z, mo.w};
#pragma unroll
            for (int j = 0; j < 4; j++)
                if (moa[j] * inv >= vth) bits4[k] |= (1u << (8 * j + 7));
        }
    }

    // ---------------- spike counts via popc (packed 2x16-bit) -------------
    {
        unsigned int packed[4];
#pragma unroll
        for (int q = 0; q < 4; q++) {
            unsigned int c_lo = 0, c_hi = 0;
            unsigned int m_lo = 0x01010101u << (2 * q);
            unsigned int m_hi = 0x01010101u << (2 * q + 1);
#pragma unroll
            for (int k = 0; k < KG; k++) {
                c_lo += __popc(bits4[k] & m_lo);
                c_hi += __popc(bits4[k] & m_hi);
            }
            packed[q] = c_lo | (c_hi << 16);     // block count <= 32768: fits
        }
#pragma unroll
        for (int q = 0; q < 4; q++) {
            unsigned int v = packed[q];
#pragma unroll
            for (int off = 16; off > 0; off >>= 1)
                v += __shfl_xor_sync(0xffffffffu, v, off);
            if (lane == 0) s_redc[warp] = v;
            __syncthreads();
            if (warp == 0) {
                unsigned int c = s_redc[lane];
#pragma unroll
                for (int off = 16; off > 0; off >>= 1)
                    c += __shfl_xor_sync(0xffffffffu, c, off);
                if (lane == 0)
                    *(volatile unsigned int*)&g_cnt_part[b][blk][q] = c;
            }
            __syncthreads();
        }
        if (warp == 0 && lane == 0) {
            __threadfence();
            unsigned int* bar = &g_bar[T_STEPS * BATCH + b];
            unsigned int old = atomicAdd(bar, 1u);
            unsigned int rel = (old | 7u) + 1u;
            volatile unsigned int* ctr = bar;
            while (*ctr < rel) { }
        }
        __syncthreads();
    }

    // ---------------- tiny attention MLP (warp 0, per batch) --------------
    if (warp == 0) {
        float summ[T_STEPS];
#pragma unroll
        for (int q = 0; q < 4; q++) {
            unsigned int lo = 0, hi = 0;
            if (lane < BLKS_PER_BATCH) {
                unsigned int v = *(volatile unsigned int*)&g_cnt_part[b][lane][q];
                lo = v & 0xffffu;                 // unpack BEFORE cross-block sum
                hi = v >> 16;
            }
#pragma unroll
            for (int off = 16; off > 0; off >>= 1) {
                lo += __shfl_xor_sync(0xffffffffu, lo, off);
                hi += __shfl_xor_sync(0xffffffffu, hi, off);
            }
            summ[2 * q]     = (float)lo * (1.0f / (float)FDIM);
            summ[2 * q + 1] = (float)hi * (1.0f / (float)FDIM);
        }
#pragma unroll
        for (int r = 0; r < 8; r++) {
            int idx = r * 32 + lane;
            float acc = b1[idx];
#pragma unroll
            for (int t = 0; t < T_STEPS; t++)
                acc += summ[t] * W1[idx * T_STEPS + t];
            s_h[idx] = fmaxf(acc, 0.0f);
        }
        __syncwarp();
        {
            float acc = b2[lane];
            const int hb = (lane >> 3) * HID;
            const float* w2p = W2 + lane * HID;
#pragma unroll
            for (int hd = 0; hd < HID; hd++)
                acc += s_h[hb + hd] * w2p[hd];
            s_maps[lane] = acc * att_w[lane >> 3];
        }
        __syncwarp();
        if (lane == 0) {
            float w[T_STEPS];
            float mx = -1e30f;
#pragma unroll
            for (int t = 0; t < T_STEPS; t++) {
                w[t] = s_maps[t] + s_maps[8 + t] + s_maps[16 + t] + s_maps[24 + t];
                mx = fmaxf(mx, w[t]);
            }
            float ssum = 0.0f;
#pragma unroll
            for (int t = 0; t < T_STEPS; t++) { w[t] = expf(w[t] - mx); ssum += w[t]; }
            float invs = 1.0f / ssum;
#pragma unroll
            for (int t = 0; t < T_STEPS; t++) s_aw[t] = w[t] * invs;
        }
    }
    __syncthreads();

    float aw[T_STEPS];
#pragma unroll
    for (int t = 0; t < T_STEPS; t++) aw[t] = s_aw[t];

    // ---------------- output: out[b,f] = sum_t aw[t]*spike(t,f) -----------
    float4* op = reinterpret_cast<float4*>(out + (size_t)b * FDIM + f0);
#pragma unroll
    for (int k = 0; k < KG; k++) {
        unsigned int bt = bits4[k];
        float o[4];
#pragma unroll
        for (int j = 0; j < 4; j++) {
            float v = 0.0f;
#pragma unroll
            for (int t = 0; t < T_STEPS; t++)
                v += ((bt >> (8 * j + t)) & 1u) ? aw[t] : 0.0f;
            o[j] = v;
        }
        op[k * NTHREADS + tid] = make_float4(o[0], o[1], o[2], o[3]);
    }
}

extern "C" void kernel_launch(void* const* d_in, const int* in_sizes, int n_in,
                              void* d_out, int out_size) {
    (void)in_sizes; (void)n_in; (void)out_size;
    cudaFuncSetAttribute(bispike_kernel,
                         cudaFuncAttributeMaxDynamicSharedMemorySize, SMEM_DYN);
    bispike_kernel<<<NBLOCKS, NTHREADS, SMEM_DYN>>>(
        (const float*)d_in[0],   // x
        (const float*)d_in[1],   // decay_param
        (const float*)d_in[2],   // v_th
        (const float*)d_in[3],   // W1
        (const float*)d_in[4],   // b1
        (const float*)d_in[5],   // W2
        (const float*)d_in[6],   // b2
        (const float*)d_in[7],   // att_w
        (float*)d_out);
}